// round 4
// baseline (speedup 1.0000x reference)
#include <cuda_runtime.h>

// Problem constants
#define BB 16
#define CC 512
#define GG 32
#define TT 180
#define NN 1024   // H*W
#define FF 1024
#define SCALE 0.04419417382415922f  // 512^-0.5
#define EPSF 1e-6f

// ---------------- scratch (no allocs allowed) ----------------
__device__ __align__(16) float g_part[32 * 512];      // partial column sums of wq
__device__ __align__(16) float g_wa[512];             // wqs[c]*gamma[c]
__device__ __align__(16) float g_wg[32];              // per-group sum of wa
__device__ __align__(16) float g_Wsum[512];           // row sums of wo
__device__ float g_const1;                            // sum(wqs*beta) + sum(bq)
__device__ __align__(16) float g_P[BB * GG * NN];     // 2MB partial channel sums
__device__ float g_sum[BB * GG];
__device__ float g_sq[BB * GG];
__device__ float g_rs[BB * GG];
__device__ float g_d[BB];
__device__ __align__(16) float g_k[BB * FF];
__device__ __align__(16) float g_v[BB * FF];
__device__ int g_ctr1 = 0;   // k1 last-block ticket
__device__ int g_ctr2 = 0;   // k23 (k2-part) last-block ticket

// ---------------- K1: weight reductions, fully fused ----------------
// grid 32, block 512. Block j reduces 16 rows of wq into column partials and
// 16 row-sums of wo. The LAST arriving block finalizes (old k1b).
__global__ void k1(const float* __restrict__ wq, const float* __restrict__ wo,
                   const float* __restrict__ gamma, const float* __restrict__ beta,
                   const float* __restrict__ bq) {
    int j = blockIdx.x;
    int c = threadIdx.x;
    float s = 0.f;
#pragma unroll
    for (int o = 0; o < 16; o++) s += wq[(j * 16 + o) * 512 + c];
    g_part[j * 512 + c] = s;

    int w = threadIdx.x >> 5, lane = threadIdx.x & 31;
    const float* row = wo + (j * 16 + w) * 512;
    float r = 0.f;
    for (int t = lane; t < 512; t += 32) r += row[t];
#pragma unroll
    for (int off = 16; off; off >>= 1) r += __shfl_down_sync(0xffffffffu, r, off);
    if (lane == 0) g_Wsum[j * 16 + w] = r;

    // ---- last-block election (no spin; every block terminates) ----
    __syncthreads();
    __threadfence();
    __shared__ int isLast;
    if (threadIdx.x == 0) isLast = (atomicAdd(&g_ctr1, 1) == 31);
    __syncthreads();
    if (!isLast) return;
    __threadfence();

    // ---- finalize (old k1b), 512 threads ----
    float wqs = 0.f;
#pragma unroll 8
    for (int jj = 0; jj < 32; jj++) wqs += g_part[jj * 512 + c];
    float wa = wqs * gamma[c];
    g_wa[c] = wa;

    __shared__ float sm[512];
    sm[c] = wqs * beta[c] + bq[c];
    __syncthreads();
    for (int st = 256; st; st >>= 1) {
        if (c < st) sm[c] += sm[c + st];
        __syncthreads();
    }
    if (c == 0) { g_const1 = sm[0]; g_ctr1 = 0; }  // reset ticket for replay

    float wgv = wa;
#pragma unroll
    for (int off = 8; off; off >>= 1) wgv += __shfl_down_sync(0xffffffffu, wgv, off, 16);
    if ((c & 15) == 0) g_wg[c >> 4] = wgv;
}

// ---------------- K23: (k2 stats+partials) ∪ (k3 k/v GEMM); last k2-block does k4 ----
// grid 640, block 256.
__global__ void k23(const float* __restrict__ x, const float* __restrict__ cond,
                    const float* __restrict__ wk, const float* __restrict__ bk,
                    const float* __restrict__ wv, const float* __restrict__ bv) {
    __shared__ float smem[2 * 16 * 181];   // 23.2KB; k2 aliases the front
    int t = threadIdx.x;

    if (blockIdx.x < 512) {
        // ---- k2 body ----
        int bg = blockIdx.x;
        int g = bg & 31;
        const float4* xs = (const float4*)x + (size_t)bg * 16 * 256;

        float4 p = make_float4(0.f, 0.f, 0.f, 0.f);
        float sum = 0.f, sq = 0.f;
#pragma unroll
        for (int c = 0; c < 16; c++) {
            float w = g_wa[g * 16 + c];
            float4 v = xs[c * 256 + t];
            sum += v.x + v.y + v.z + v.w;
            sq += v.x * v.x + v.y * v.y + v.z * v.z + v.w * v.w;
            p.x += w * v.x; p.y += w * v.y; p.z += w * v.z; p.w += w * v.w;
        }
        ((float4*)g_P)[bg * 256 + t] = p;

        float* s1 = smem;
        float* s2 = smem + 256;
        s1[t] = sum; s2[t] = sq;
        __syncthreads();
        for (int st = 128; st; st >>= 1) {
            if (t < st) { s1[t] += s1[t + st]; s2[t] += s2[t + st]; }
            __syncthreads();
        }
        if (t == 0) { g_sum[bg] = s1[0]; g_sq[bg] = s2[0]; }

        // ---- last-block election over the 512 k2 blocks ----
        __syncthreads();
        __threadfence();
        __shared__ int isLast;
        if (t == 0) isLast = (atomicAdd(&g_ctr2, 1) == 511);
        __syncthreads();
        if (!isLast) return;
        __threadfence();

        // ---- old k4: rs for all 512 (b,g); d[b] per batch ----
        float* tmp = smem;  // reuse, need 512 floats
        const float inv = 1.f / 16384.f;
#pragma unroll
        for (int i = 0; i < 2; i++) {
            int idx = t + 256 * i;                 // (b*32+g)
            float mean = g_sum[idx] * inv;
            float var = g_sq[idx] * inv - mean * mean;
            float rs = rsqrtf(var + EPSF);
            g_rs[idx] = rs;
            tmp[idx] = mean * rs * g_wg[idx & 31];
        }
        __syncthreads();
        int w = t >> 5, lane = t & 31;
        float c1 = g_const1;
#pragma unroll
        for (int i = 0; i < 2; i++) {
            int b = w + 8 * i;                     // 8 warps x 2 = 16 batches
            float v = tmp[b * 32 + lane];
#pragma unroll
            for (int off = 16; off; off >>= 1) v += __shfl_down_sync(0xffffffffu, v, off);
            if (lane == 0) g_d[b] = c1 - v;
        }
        if (t == 0) g_ctr2 = 0;  // reset ticket for replay
    } else {
        // ---- k3 body: tiled smem GEMM for k/v ----
        int bx = blockIdx.x - 512;        // 0..127
        int mat = bx >> 6;                // 0 = k, 1 = v
        int ft = bx & 63;                 // f-tile of 16
        const float* W    = mat ? wv : wk;
        const float* bias = mat ? bv : bk;
        float* out        = mat ? g_v : g_k;

        float (*sw)[181] = (float (*)[181])smem;
        float (*sc)[181] = (float (*)[181])(smem + 16 * 181);
        int f0 = ft * 16;
        for (int i = t; i < 16 * 180; i += 256) {
            int r = i / 180, cc2 = i - r * 180;
            sw[r][cc2] = W[(size_t)(f0 + r) * TT + cc2];
            sc[r][cc2] = cond[r * TT + cc2];
        }
        __syncthreads();

        int fo = t & 15, bb = t >> 4;
        float acc = 0.f;
#pragma unroll 4
        for (int k = 0; k < TT; k++) acc += sw[fo][k] * sc[bb][k];
        out[bb * FF + f0 + fo] = acc + bias[f0 + fo];
    }
}

// ---------------- K56: softmax-weighted average + output elementwise, fused ----------
// grid 512 (b = blk>>5, 32-col chunk = blk&31), block 256 (8 warps).
// Phase 1: S + softmax avg -> sA[32] (32K exps/block).
// Phase 2: out[b, :, n0:n0+32] = x + Wsum[c]*A[n] + bo[c]   (64KB read + 64KB write)
__global__ void k56(const float* __restrict__ x, const float* __restrict__ bo,
                    float* __restrict__ out) {
    __shared__ float sk[1024], sv[1024];
    __shared__ float sA[32], sS[32], srs[32];
    int b  = blockIdx.x >> 5;
    int ch = blockIdx.x & 31;
    int n0 = ch * 32;
    int t = threadIdx.x;

    ((float4*)sk)[t] = ((const float4*)(g_k + b * FF))[t];
    ((float4*)sv)[t] = ((const float4*)(g_v + b * FF))[t];
    if (t < 32) srs[t] = g_rs[b * 32 + t];
    float d = g_d[b];
    __syncthreads();

    int w = t >> 5, lane = t & 31;
    // S for 4 n's per warp (lane = group)
#pragma unroll
    for (int i = 0; i < 4; i++) {
        int n = w * 4 + i;
        float ps = srs[lane] * __ldg(&g_P[((size_t)b * 32 + lane) * NN + n0 + n]);
#pragma unroll
        for (int off = 16; off; off >>= 1) ps += __shfl_xor_sync(0xffffffffu, ps, off);
        if (lane == 0) sS[n] = (ps + d) * SCALE;
    }
    __syncthreads();

    // softmax-weighted average over f (no max-sub: logits tiny by construction)
#pragma unroll
    for (int i = 0; i < 4; i++) {
        int n = w * 4 + i;
        float s = sS[n];
        float l = 0.f, acc = 0.f;
#pragma unroll
        for (int j = 0; j < 8; j++) {
            float4 k4v = ((float4*)sk)[j * 32 + lane];
            float4 v4  = ((float4*)sv)[j * 32 + lane];
            float e0 = __expf(s * k4v.x), e1 = __expf(s * k4v.y);
            float e2 = __expf(s * k4v.z), e3 = __expf(s * k4v.w);
            l += e0 + e1 + e2 + e3;
            acc += v4.x * e0 + v4.y * e1 + v4.z * e2 + v4.w * e3;
        }
#pragma unroll
        for (int off = 16; off; off >>= 1) {
            l   += __shfl_xor_sync(0xffffffffu, l, off);
            acc += __shfl_xor_sync(0xffffffffu, acc, off);
        }
        if (lane == 0) sA[n] = acc / l;
    }
    __syncthreads();

    // elementwise stream: 32 n = 8 float4 per channel row, 512 channels
    int f4 = t & 7, c0 = t >> 3;
    const float4* xp = (const float4*)x + ((size_t)b * 512) * 256 + ch * 8;
    float4*       op = (float4*)out     + ((size_t)b * 512) * 256 + ch * 8;
    float4 a = ((float4*)sA)[f4];
#pragma unroll
    for (int it = 0; it < 16; it++) {
        int c = c0 + 32 * it;
        float wv = g_Wsum[c];
        float bb = bo[c];
        float4 xv = xp[(size_t)c * 256 + f4];
        float4 o;
        o.x = xv.x + wv * a.x + bb;
        o.y = xv.y + wv * a.y + bb;
        o.z = xv.z + wv * a.z + bb;
        o.w = xv.w + wv * a.w + bb;
        op[(size_t)c * 256 + f4] = o;
    }
}

extern "C" void kernel_launch(void* const* d_in, const int* in_sizes, int n_in,
                              void* d_out, int out_size) {
    const float* x     = (const float*)d_in[0];
    const float* cond  = (const float*)d_in[1];
    const float* gamma = (const float*)d_in[2];
    const float* beta  = (const float*)d_in[3];
    const float* wq    = (const float*)d_in[4];
    const float* bq    = (const float*)d_in[5];
    const float* wk    = (const float*)d_in[6];
    const float* bk    = (const float*)d_in[7];
    const float* wv    = (const float*)d_in[8];
    const float* bv    = (const float*)d_in[9];
    const float* wo    = (const float*)d_in[10];
    const float* bo    = (const float*)d_in[11];
    float* out = (float*)d_out;

    k1<<<32, 512>>>(wq, wo, gamma, beta, bq);
    k23<<<640, 256>>>(x, cond, wk, bk, wv, bv);
    k56<<<512, 256>>>(x, bo, out);
}

// round 5
// speedup vs baseline: 1.1275x; 1.1275x over previous
#include <cuda_runtime.h>

// Problem constants
#define BB 16
#define CC 512
#define GG 32
#define TT 180
#define NN 1024   // H*W
#define FF 1024
#define SCALE 0.04419417382415922f  // 512^-0.5
#define EPSF 1e-6f

// ---------------- scratch (no allocs allowed) ----------------
__device__ __align__(16) float g_part[128 * 512];     // partial column sums of wq (256KB)
__device__ __align__(16) float g_wa[512];             // wqs[c]*gamma[c]
__device__ __align__(16) float g_wg[32];              // per-group sum of wa
__device__ __align__(16) float g_Wsum[512];           // row sums of wo
__device__ float g_const1;                            // sum(wqs*beta) + sum(bq)
__device__ __align__(16) float g_P[BB * GG * NN];     // 2MB partial channel sums
__device__ float g_sum[BB * GG];
__device__ float g_sq[BB * GG];
__device__ float g_rs[BB * GG];
__device__ float g_d[BB];
__device__ __align__(16) float g_k[BB * FF];
__device__ __align__(16) float g_v[BB * FF];
__device__ int g_ctr1 = 0;   // k1 last-block ticket
__device__ int g_ctr2 = 0;   // k23 (k2-part) last-block ticket

// ---------------- K1: weight reductions, full-wave ----------------
// grid 128, block 256. Block j reduces 4 rows of wq into column partials
// (thread t owns columns t and t+256) and 4 full row-sums of wo (2 warps/row).
// The LAST arriving block finalizes: wqs -> g_wa/g_const1/g_wg.
__global__ void k1(const float* __restrict__ wq, const float* __restrict__ wo,
                   const float* __restrict__ gamma, const float* __restrict__ beta,
                   const float* __restrict__ bq) {
    int j = blockIdx.x;
    int t = threadIdx.x;
    int w = t >> 5, lane = t & 31;

    // wq column partials: 4 rows, 2 columns per thread
    float s0 = 0.f, s1 = 0.f;
#pragma unroll
    for (int r = 0; r < 4; r++) {
        const float* row = wq + (size_t)(j * 4 + r) * 512;
        s0 += row[t];
        s1 += row[t + 256];
    }
    g_part[j * 512 + t] = s0;
    g_part[j * 512 + t + 256] = s1;

    // wo row sums: 8 warps -> 4 rows x 2 half-rows
    {
        int row = j * 4 + (w >> 1);
        const float* rp = wo + (size_t)row * 512 + (w & 1) * 256;
        float r = 0.f;
#pragma unroll
        for (int i = 0; i < 8; i++) r += rp[lane + 32 * i];
#pragma unroll
        for (int off = 16; off; off >>= 1) r += __shfl_down_sync(0xffffffffu, r, off);
        __shared__ float swo[8];
        if (lane == 0) swo[w] = r;
        __syncthreads();
        if (t < 4) g_Wsum[j * 4 + t] = swo[2 * t] + swo[2 * t + 1];
    }

    // ---- last-block election (no spin; every block terminates) ----
    __syncthreads();
    __threadfence();
    __shared__ int isLast;
    if (t == 0) isLast = (atomicAdd(&g_ctr1, 1) == 127);
    __syncthreads();
    if (!isLast) return;
    __threadfence();

    // ---- finalize: sum 128 partials per column (reads L2) ----
    float wqs0 = 0.f, wqs1 = 0.f;
#pragma unroll 8
    for (int jj = 0; jj < 128; jj++) {
        wqs0 += g_part[jj * 512 + t];
        wqs1 += g_part[jj * 512 + t + 256];
    }
    float wa0 = wqs0 * gamma[t];
    float wa1 = wqs1 * gamma[t + 256];
    g_wa[t] = wa0;
    g_wa[t + 256] = wa1;

    // const1 = sum_c wqs[c]*beta[c] + bq[c]
    __shared__ float sm[256];
    sm[t] = wqs0 * beta[t] + bq[t] + wqs1 * beta[t + 256] + bq[t + 256];
    __syncthreads();
    for (int st = 128; st; st >>= 1) {
        if (t < st) sm[t] += sm[t + st];
        __syncthreads();
    }
    if (t == 0) { g_const1 = sm[0]; g_ctr1 = 0; }  // reset ticket for replay

    // per-group (16-ch) sums of wa: threads t cover groups 0-15 (wa0) and 16-31 (wa1)
    float wg0 = wa0, wg1 = wa1;
#pragma unroll
    for (int off = 8; off; off >>= 1) {
        wg0 += __shfl_down_sync(0xffffffffu, wg0, off, 16);
        wg1 += __shfl_down_sync(0xffffffffu, wg1, off, 16);
    }
    if ((t & 15) == 0) {
        g_wg[t >> 4] = wg0;
        g_wg[16 + (t >> 4)] = wg1;
    }
}

// ---------------- K23: (k2 stats+partials) ∪ (k3 k/v GEMM); last k2-block does k4 ----
// grid 640, block 256.
__global__ void k23(const float* __restrict__ x, const float* __restrict__ cond,
                    const float* __restrict__ wk, const float* __restrict__ bk,
                    const float* __restrict__ wv, const float* __restrict__ bv) {
    __shared__ float smem[2 * 16 * 181];   // 23.2KB; k2 aliases the front
    int t = threadIdx.x;

    if (blockIdx.x < 512) {
        // ---- k2 body ----
        int bg = blockIdx.x;
        int g = bg & 31;
        const float4* xs = (const float4*)x + (size_t)bg * 16 * 256;

        float4 p = make_float4(0.f, 0.f, 0.f, 0.f);
        float sum = 0.f, sq = 0.f;
#pragma unroll
        for (int c = 0; c < 16; c++) {
            float w = g_wa[g * 16 + c];
            float4 v = xs[c * 256 + t];
            sum += v.x + v.y + v.z + v.w;
            sq += v.x * v.x + v.y * v.y + v.z * v.z + v.w * v.w;
            p.x += w * v.x; p.y += w * v.y; p.z += w * v.z; p.w += w * v.w;
        }
        ((float4*)g_P)[bg * 256 + t] = p;

        float* s1 = smem;
        float* s2 = smem + 256;
        s1[t] = sum; s2[t] = sq;
        __syncthreads();
        for (int st = 128; st; st >>= 1) {
            if (t < st) { s1[t] += s1[t + st]; s2[t] += s2[t + st]; }
            __syncthreads();
        }
        if (t == 0) { g_sum[bg] = s1[0]; g_sq[bg] = s2[0]; }

        // ---- last-block election over the 512 k2 blocks ----
        __syncthreads();
        __threadfence();
        __shared__ int isLast;
        if (t == 0) isLast = (atomicAdd(&g_ctr2, 1) == 511);
        __syncthreads();
        if (!isLast) return;
        __threadfence();

        // ---- old k4: rs for all 512 (b,g); d[b] per batch ----
        float* tmp = smem;  // reuse, need 512 floats
        const float inv = 1.f / 16384.f;
#pragma unroll
        for (int i = 0; i < 2; i++) {
            int idx = t + 256 * i;                 // (b*32+g)
            float mean = g_sum[idx] * inv;
            float var = g_sq[idx] * inv - mean * mean;
            float rs = rsqrtf(var + EPSF);
            g_rs[idx] = rs;
            tmp[idx] = mean * rs * g_wg[idx & 31];
        }
        __syncthreads();
        int w = t >> 5, lane = t & 31;
        float c1 = g_const1;
#pragma unroll
        for (int i = 0; i < 2; i++) {
            int b = w + 8 * i;                     // 8 warps x 2 = 16 batches
            float v = tmp[b * 32 + lane];
#pragma unroll
            for (int off = 16; off; off >>= 1) v += __shfl_down_sync(0xffffffffu, v, off);
            if (lane == 0) g_d[b] = c1 - v;
        }
        if (t == 0) g_ctr2 = 0;  // reset ticket for replay
    } else {
        // ---- k3 body: tiled smem GEMM for k/v ----
        int bx = blockIdx.x - 512;        // 0..127
        int mat = bx >> 6;                // 0 = k, 1 = v
        int ft = bx & 63;                 // f-tile of 16
        const float* W    = mat ? wv : wk;
        const float* bias = mat ? bv : bk;
        float* out        = mat ? g_v : g_k;

        float (*sw)[181] = (float (*)[181])smem;
        float (*sc)[181] = (float (*)[181])(smem + 16 * 181);
        int f0 = ft * 16;
        for (int i = t; i < 16 * 180; i += 256) {
            int r = i / 180, cc2 = i - r * 180;
            sw[r][cc2] = W[(size_t)(f0 + r) * TT + cc2];
            sc[r][cc2] = cond[r * TT + cc2];
        }
        __syncthreads();

        int fo = t & 15, bb = t >> 4;
        float acc = 0.f;
#pragma unroll 4
        for (int k = 0; k < TT; k++) acc += sw[fo][k] * sc[bb][k];
        out[bb * FF + f0 + fo] = acc + bias[f0 + fo];
    }
}

// ---------------- K56: softmax-weighted average + output elementwise, fused ----------
// grid 512 (b = blk>>5, 32-col chunk = blk&31), block 256 (8 warps).
__global__ void k56(const float* __restrict__ x, const float* __restrict__ bo,
                    float* __restrict__ out) {
    __shared__ float sk[1024], sv[1024];
    __shared__ float sA[32], sS[32], srs[32];
    int b  = blockIdx.x >> 5;
    int ch = blockIdx.x & 31;
    int n0 = ch * 32;
    int t = threadIdx.x;

    ((float4*)sk)[t] = ((const float4*)(g_k + b * FF))[t];
    ((float4*)sv)[t] = ((const float4*)(g_v + b * FF))[t];
    if (t < 32) srs[t] = g_rs[b * 32 + t];
    float d = g_d[b];
    __syncthreads();

    int w = t >> 5, lane = t & 31;
    // S for 4 n's per warp (lane = group)
#pragma unroll
    for (int i = 0; i < 4; i++) {
        int n = w * 4 + i;
        float ps = srs[lane] * __ldg(&g_P[((size_t)b * 32 + lane) * NN + n0 + n]);
#pragma unroll
        for (int off = 16; off; off >>= 1) ps += __shfl_xor_sync(0xffffffffu, ps, off);
        if (lane == 0) sS[n] = (ps + d) * SCALE;
    }
    __syncthreads();

    // softmax-weighted average over f (no max-sub: logits tiny by construction)
#pragma unroll
    for (int i = 0; i < 4; i++) {
        int n = w * 4 + i;
        float s = sS[n];
        float l = 0.f, acc = 0.f;
#pragma unroll
        for (int j = 0; j < 8; j++) {
            float4 k4v = ((float4*)sk)[j * 32 + lane];
            float4 v4  = ((float4*)sv)[j * 32 + lane];
            float e0 = __expf(s * k4v.x), e1 = __expf(s * k4v.y);
            float e2 = __expf(s * k4v.z), e3 = __expf(s * k4v.w);
            l += e0 + e1 + e2 + e3;
            acc += v4.x * e0 + v4.y * e1 + v4.z * e2 + v4.w * e3;
        }
#pragma unroll
        for (int off = 16; off; off >>= 1) {
            l   += __shfl_xor_sync(0xffffffffu, l, off);
            acc += __shfl_xor_sync(0xffffffffu, acc, off);
        }
        if (lane == 0) sA[n] = acc / l;
    }
    __syncthreads();

    // elementwise stream: 32 n = 8 float4 per channel row, 512 channels
    int f4 = t & 7, c0 = t >> 3;
    const float4* xp = (const float4*)x + ((size_t)b * 512) * 256 + ch * 8;
    float4*       op = (float4*)out     + ((size_t)b * 512) * 256 + ch * 8;
    float4 a = ((float4*)sA)[f4];
#pragma unroll
    for (int it = 0; it < 16; it++) {
        int c = c0 + 32 * it;
        float wv = g_Wsum[c];
        float bb = bo[c];
        float4 xv = xp[(size_t)c * 256 + f4];
        float4 o;
        o.x = xv.x + wv * a.x + bb;
        o.y = xv.y + wv * a.y + bb;
        o.z = xv.z + wv * a.z + bb;
        o.w = xv.w + wv * a.w + bb;
        op[(size_t)c * 256 + f4] = o;
    }
}

extern "C" void kernel_launch(void* const* d_in, const int* in_sizes, int n_in,
                              void* d_out, int out_size) {
    const float* x     = (const float*)d_in[0];
    const float* cond  = (const float*)d_in[1];
    const float* gamma = (const float*)d_in[2];
    const float* beta  = (const float*)d_in[3];
    const float* wq    = (const float*)d_in[4];
    const float* bq    = (const float*)d_in[5];
    const float* wk    = (const float*)d_in[6];
    const float* bk    = (const float*)d_in[7];
    const float* wv    = (const float*)d_in[8];
    const float* bv    = (const float*)d_in[9];
    const float* wo    = (const float*)d_in[10];
    const float* bo    = (const float*)d_in[11];
    float* out = (float*)d_out;

    k1<<<128, 256>>>(wq, wo, gamma, beta, bq);
    k23<<<640, 256>>>(x, cond, wk, bk, wv, bv);
    k56<<<512, 256>>>(x, bo, out);
}